// round 15
// baseline (speedup 1.0000x reference)
#include <cuda_runtime.h>

// FINAL — converged at the HBM ceiling. LIF neuron, T=4 unrolled.
// 2 adjacent neurons per thread: one ld.global.cs.v8.f32 per input array
// and ONE st.global.cs.v8.f32 for both outputs (3 memory instr/thread).
// Layout [B, N, T], T innermost -> one float4 per neuron; per-thread pair
// is 32B contiguous, each warp access covers a contiguous 1KB segment.
// Streaming (.cs) everywhere: strict read-once/write-once workload.
//
// Convergence record (GB300, kernel time @ DRAM SOL):
//   v8 ld+st (this):      108.6 / 108.8 / 109.5us @ 87.5-88.1%  <- best
//   f4x2 blk256:          108.6-110.1us @ 87-88% (5 reps)
//   f4x1/v8-ld/f4x4/blk512: 109.3-110.4us
//   persistent grid-stride: 120.5us (regression: flat oversubscription wins)
// Traffic (512MB read + 256MB write fp32) is irreducible; ~7.0 TB/s achieved
// is the HBM3e 2R:1W streaming ceiling (turnaround/refresh eat the last 12%).
// 768MB / 7.0TB/s ~= 109us kernel = measured floor. Held as final.

#define TAU 0.25f

__device__ __forceinline__ float4 lif4(float4 xv, float4 lv, float thre)
{
    float4 ov;
    float u = xv.x + lv.x;                 // t=0: u0=0 -> no decay term
    float o = (u > thre) ? u : 0.0f;
    ov.x = o;
    float reset = (o > thre) ? 0.0f : 1.0f;
    u = TAU * u * reset + xv.y + lv.y;     // t=1
    o = (u > thre) ? u : 0.0f;
    ov.y = o;
    reset = (o > thre) ? 0.0f : 1.0f;
    u = TAU * u * reset + xv.z + lv.z;     // t=2
    o = (u > thre) ? u : 0.0f;
    ov.z = o;
    reset = (o > thre) ? 0.0f : 1.0f;
    u = TAU * u * reset + xv.w + lv.w;     // t=3
    o = (u > thre) ? u : 0.0f;
    ov.w = o;
    return ov;
}

__device__ __forceinline__ void ldg256cs(const float* p, float4& a, float4& b)
{
    asm volatile(
        "ld.global.cs.v8.f32 {%0,%1,%2,%3,%4,%5,%6,%7}, [%8];"
        : "=f"(a.x), "=f"(a.y), "=f"(a.z), "=f"(a.w),
          "=f"(b.x), "=f"(b.y), "=f"(b.z), "=f"(b.w)
        : "l"(p));
}

__device__ __forceinline__ void stg256cs(float* p, float4 a, float4 b)
{
    asm volatile(
        "st.global.cs.v8.f32 [%0], {%1,%2,%3,%4,%5,%6,%7,%8};"
        :: "l"(p),
           "f"(a.x), "f"(a.y), "f"(a.z), "f"(a.w),
           "f"(b.x), "f"(b.y), "f"(b.z), "f"(b.w)
        : "memory");
}

// Fast path: grid*blockDim*2 == n exactly; no predicates.
__global__ __launch_bounds__(256) void lif_kernel_v8st(
    const float* __restrict__ x,
    const float* __restrict__ lat,
    const float* __restrict__ w,
    float* __restrict__ out)
{
    long long g = (long long)blockIdx.x * blockDim.x + threadIdx.x;
    long long off = g * 8;     // 2 adjacent float4s = 8 floats, 32B aligned

    const float thre = tanhf(w[0]);

    float4 x0, x1, l0, l1;
    ldg256cs(x   + off, x0, x1);
    ldg256cs(lat + off, l0, l1);

    float4 o0 = lif4(x0, l0, thre);
    float4 o1 = lif4(x1, l1, thre);

    stg256cs(out + off, o0, o1);
}

// Fallback: one float4 per thread, predicated (general sizes).
__global__ __launch_bounds__(256) void lif_kernel_f4(
    const float4* __restrict__ x,
    const float4* __restrict__ lat,
    const float* __restrict__ w,
    float4* __restrict__ out,
    int n)
{
    int i = blockIdx.x * blockDim.x + threadIdx.x;
    if (i >= n) return;
    const float thre = tanhf(w[0]);
    float4 xv = __ldcs(&x[i]);
    float4 lv = __ldcs(&lat[i]);
    __stcs(&out[i], lif4(xv, lv, thre));
}

extern "C" void kernel_launch(void* const* d_in, const int* in_sizes, int n_in,
                              void* d_out, int out_size)
{
    const float* x   = (const float*)d_in[0];  // [B, N, T] float32, T=4
    const float* lat = (const float*)d_in[1];
    const float* w   = (const float*)d_in[2];  // scalar
    float* out = (float*)d_out;

    int n = in_sizes[0] / 4;     // neurons (B*N); one float4 each
    int block = 256;
    int per_block = block * 2;   // 2 neurons per thread

    if (n % per_block == 0) {
        lif_kernel_v8st<<<n / per_block, block>>>(x, lat, w, out);
    } else {
        lif_kernel_f4<<<(n + block - 1) / block, block>>>(
            (const float4*)x, (const float4*)lat, w, (float4*)out, n);
    }
}

// round 16
// speedup vs baseline: 1.0098x; 1.0098x over previous
#include <cuda_runtime.h>

// LIF neuron, T=4 unrolled — v8 loads (.cs) + v8 store with .wt probe.
// Identical to the converged optimum except the store cache-op:
// st.global.wt.v8 (write-through, no dirty L2 line / writeback) vs .cs.
// Tests whether DRAM 2R:1W turnaround loss is sensitive to writeback
// scheduling — the last unswept SM-side knob.

#define TAU 0.25f

__device__ __forceinline__ float4 lif4(float4 xv, float4 lv, float thre)
{
    float4 ov;
    float u = xv.x + lv.x;                 // t=0: u0=0 -> no decay term
    float o = (u > thre) ? u : 0.0f;
    ov.x = o;
    float reset = (o > thre) ? 0.0f : 1.0f;
    u = TAU * u * reset + xv.y + lv.y;     // t=1
    o = (u > thre) ? u : 0.0f;
    ov.y = o;
    reset = (o > thre) ? 0.0f : 1.0f;
    u = TAU * u * reset + xv.z + lv.z;     // t=2
    o = (u > thre) ? u : 0.0f;
    ov.z = o;
    reset = (o > thre) ? 0.0f : 1.0f;
    u = TAU * u * reset + xv.w + lv.w;     // t=3
    o = (u > thre) ? u : 0.0f;
    ov.w = o;
    return ov;
}

__device__ __forceinline__ void ldg256cs(const float* p, float4& a, float4& b)
{
    asm volatile(
        "ld.global.cs.v8.f32 {%0,%1,%2,%3,%4,%5,%6,%7}, [%8];"
        : "=f"(a.x), "=f"(a.y), "=f"(a.z), "=f"(a.w),
          "=f"(b.x), "=f"(b.y), "=f"(b.z), "=f"(b.w)
        : "l"(p));
}

__device__ __forceinline__ void stg256wt(float* p, float4 a, float4 b)
{
    asm volatile(
        "st.global.wt.v8.f32 [%0], {%1,%2,%3,%4,%5,%6,%7,%8};"
        :: "l"(p),
           "f"(a.x), "f"(a.y), "f"(a.z), "f"(a.w),
           "f"(b.x), "f"(b.y), "f"(b.z), "f"(b.w)
        : "memory");
}

// Fast path: grid*blockDim*2 == n exactly; no predicates.
__global__ __launch_bounds__(256) void lif_kernel_v8wt(
    const float* __restrict__ x,
    const float* __restrict__ lat,
    const float* __restrict__ w,
    float* __restrict__ out)
{
    long long g = (long long)blockIdx.x * blockDim.x + threadIdx.x;
    long long off = g * 8;     // 2 adjacent float4s = 8 floats, 32B aligned

    const float thre = tanhf(w[0]);

    float4 x0, x1, l0, l1;
    ldg256cs(x   + off, x0, x1);
    ldg256cs(lat + off, l0, l1);

    float4 o0 = lif4(x0, l0, thre);
    float4 o1 = lif4(x1, l1, thre);

    stg256wt(out + off, o0, o1);
}

// Fallback: one float4 per thread, predicated (general sizes).
__global__ __launch_bounds__(256) void lif_kernel_f4(
    const float4* __restrict__ x,
    const float4* __restrict__ lat,
    const float* __restrict__ w,
    float4* __restrict__ out,
    int n)
{
    int i = blockIdx.x * blockDim.x + threadIdx.x;
    if (i >= n) return;
    const float thre = tanhf(w[0]);
    float4 xv = __ldcs(&x[i]);
    float4 lv = __ldcs(&lat[i]);
    __stcs(&out[i], lif4(xv, lv, thre));
}

extern "C" void kernel_launch(void* const* d_in, const int* in_sizes, int n_in,
                              void* d_out, int out_size)
{
    const float* x   = (const float*)d_in[0];  // [B, N, T] float32, T=4
    const float* lat = (const float*)d_in[1];
    const float* w   = (const float*)d_in[2];  // scalar
    float* out = (float*)d_out;

    int n = in_sizes[0] / 4;     // neurons (B*N); one float4 each
    int block = 256;
    int per_block = block * 2;   // 2 neurons per thread

    if (n % per_block == 0) {
        lif_kernel_v8wt<<<n / per_block, block>>>(x, lat, w, out);
    } else {
        lif_kernel_f4<<<(n + block - 1) / block, block>>>(
            (const float4*)x, (const float4*)lat, w, (float4*)out, n);
    }
}

// round 17
// speedup vs baseline: 1.0131x; 1.0033x over previous
#include <cuda_runtime.h>

// FINAL — converged at the HBM ceiling. LIF neuron, T=4 unrolled.
// 2 adjacent neurons per thread: one ld.global.cs.v8.f32 per input array
// and ONE st.global.cs.v8.f32 for both outputs (3 memory instr/thread).
// Layout [B, N, T], T innermost -> one float4 per neuron; per-thread pair
// is 32B contiguous, each warp access covers a contiguous 1KB segment.
// Streaming (.cs) everywhere: strict read-once/write-once workload.
//
// Full sweep complete (GB300, kernel time @ DRAM SOL):
//   v8 ld+st .cs (this):  108.6 / 108.8 / 109.5 / 109.7us @ 87-88% <- best
//   v8 ld + .wt st:       109.9us (writeback scheduling: invariant)
//   f4x2 blk256:          108.6-110.1us (5 reps)
//   f4x1/v8-ld/f4x4/blk512: 109.3-110.4us
//   persistent grid-stride: 120.5us (flat oversubscription wins)
// Knobs swept: batch depth (1/2/4), vector width (128/256b ld+st), block
// (256/512), cache policy (default/.cs/.wt), flat vs persistent grid.
// Traffic (512MB read + 256MB write fp32) is irreducible; ~7.0 TB/s achieved
// is the HBM3e 2R:1W streaming ceiling (turnaround/refresh eat the last 12%).
// 768MB / 7.0TB/s ~= 109us kernel = measured floor. Held as final.

#define TAU 0.25f

__device__ __forceinline__ float4 lif4(float4 xv, float4 lv, float thre)
{
    float4 ov;
    float u = xv.x + lv.x;                 // t=0: u0=0 -> no decay term
    float o = (u > thre) ? u : 0.0f;
    ov.x = o;
    float reset = (o > thre) ? 0.0f : 1.0f;
    u = TAU * u * reset + xv.y + lv.y;     // t=1
    o = (u > thre) ? u : 0.0f;
    ov.y = o;
    reset = (o > thre) ? 0.0f : 1.0f;
    u = TAU * u * reset + xv.z + lv.z;     // t=2
    o = (u > thre) ? u : 0.0f;
    ov.z = o;
    reset = (o > thre) ? 0.0f : 1.0f;
    u = TAU * u * reset + xv.w + lv.w;     // t=3
    o = (u > thre) ? u : 0.0f;
    ov.w = o;
    return ov;
}

__device__ __forceinline__ void ldg256cs(const float* p, float4& a, float4& b)
{
    asm volatile(
        "ld.global.cs.v8.f32 {%0,%1,%2,%3,%4,%5,%6,%7}, [%8];"
        : "=f"(a.x), "=f"(a.y), "=f"(a.z), "=f"(a.w),
          "=f"(b.x), "=f"(b.y), "=f"(b.z), "=f"(b.w)
        : "l"(p));
}

__device__ __forceinline__ void stg256cs(float* p, float4 a, float4 b)
{
    asm volatile(
        "st.global.cs.v8.f32 [%0], {%1,%2,%3,%4,%5,%6,%7,%8};"
        :: "l"(p),
           "f"(a.x), "f"(a.y), "f"(a.z), "f"(a.w),
           "f"(b.x), "f"(b.y), "f"(b.z), "f"(b.w)
        : "memory");
}

// Fast path: grid*blockDim*2 == n exactly; no predicates.
__global__ __launch_bounds__(256) void lif_kernel_v8st(
    const float* __restrict__ x,
    const float* __restrict__ lat,
    const float* __restrict__ w,
    float* __restrict__ out)
{
    long long g = (long long)blockIdx.x * blockDim.x + threadIdx.x;
    long long off = g * 8;     // 2 adjacent float4s = 8 floats, 32B aligned

    const float thre = tanhf(w[0]);

    float4 x0, x1, l0, l1;
    ldg256cs(x   + off, x0, x1);
    ldg256cs(lat + off, l0, l1);

    float4 o0 = lif4(x0, l0, thre);
    float4 o1 = lif4(x1, l1, thre);

    stg256cs(out + off, o0, o1);
}

// Fallback: one float4 per thread, predicated (general sizes).
__global__ __launch_bounds__(256) void lif_kernel_f4(
    const float4* __restrict__ x,
    const float4* __restrict__ lat,
    const float* __restrict__ w,
    float4* __restrict__ out,
    int n)
{
    int i = blockIdx.x * blockDim.x + threadIdx.x;
    if (i >= n) return;
    const float thre = tanhf(w[0]);
    float4 xv = __ldcs(&x[i]);
    float4 lv = __ldcs(&lat[i]);
    __stcs(&out[i], lif4(xv, lv, thre));
}

extern "C" void kernel_launch(void* const* d_in, const int* in_sizes, int n_in,
                              void* d_out, int out_size)
{
    const float* x   = (const float*)d_in[0];  // [B, N, T] float32, T=4
    const float* lat = (const float*)d_in[1];
    const float* w   = (const float*)d_in[2];  // scalar
    float* out = (float*)d_out;

    int n = in_sizes[0] / 4;     // neurons (B*N); one float4 each
    int block = 256;
    int per_block = block * 2;   // 2 neurons per thread

    if (n % per_block == 0) {
        lif_kernel_v8st<<<n / per_block, block>>>(x, lat, w, out);
    } else {
        lif_kernel_f4<<<(n + block - 1) / block, block>>>(
            (const float4*)x, (const float4*)lat, w, (float4*)out, n);
    }
}